// round 6
// baseline (speedup 1.0000x reference)
#include <cuda_runtime.h>

#define BB 64
#define HH 56
#define WW 56
#define CC 256
#define CO 64
#define NROUTES 4
#define CHUNKS 14
#define X_ELEMS (BB*HH*WW*CO)   // 12,845,056

// scratch (device globals; no allocation allowed)
__device__ float g_w2[9 * CC * NROUTES];   // a-less conv_w @ fc_w / 784
__device__ float g_const[NROUTES];          // conv_b @ fc_w + fc_b
__device__ float g_routing[BB * NROUTES];   // atomic-accumulated logits
__device__ int   g_flag;                    // w2-ready flag (reset by gather)

// ---------------------------------------------------------------------------
// Kernel 1: parity sums fused with routing contraction.
// grid 897: bid 0 = W2 duty block; bids 1..896 = one 4-row chunk each.
// Duty block: W2[k][ci][r] = (1/784)*sum_co convw[k][ci][co]*fcw[co][r],
//             g_const, zero g_routing, fence, set flag.
// Worker: stream 4 rows (float4/thread), smem-transpose to per-channel
// parity partials, fold BN, contract with W2 (spin on flag first -- by then
// it is long set), block-reduce 4 floats, atomicAdd to g_routing[b].
// ---------------------------------------------------------------------------
__global__ void reduce_route_kernel(const float4* __restrict__ in,
                                    const float* __restrict__ gamma,
                                    const float* __restrict__ beta,
                                    const float* __restrict__ mmean,
                                    const float* __restrict__ mvar,
                                    const float* __restrict__ convw,
                                    const float* __restrict__ convb,
                                    const float* __restrict__ fcw,
                                    const float* __restrict__ fcb) {
    __shared__ float sm[4 * 3 * CC];     // 12 KB
    const int t = threadIdx.x;

    if (blockIdx.x == 0) {
        // ---------------- W2 duty block (wave-1 resident: bid 0) ----------
        __shared__ float fsm[CO * NROUTES];
        if (t < CO * NROUTES) fsm[t] = fcw[t];
        g_routing[t] = 0.f;              // t covers all 256 entries
        __syncthreads();

        const int ci = t;
        #pragma unroll
        for (int k = 0; k < 9; k++) {
            const float* wrow = convw + ((size_t)k * CC + ci) * CO;
            float acc[NROUTES] = {0.f, 0.f, 0.f, 0.f};
            #pragma unroll 8
            for (int co = 0; co < CO; co++) {
                const float w = wrow[co];
                #pragma unroll
                for (int r = 0; r < NROUTES; r++)
                    acc[r] += w * fsm[co * NROUTES + r];
            }
            #pragma unroll
            for (int r = 0; r < NROUTES; r++)
                g_w2[(k * CC + ci) * NROUTES + r] = acc[r] * (1.0f / 784.0f);
        }
        if (t < NROUTES) {
            float c = fcb[t];
            for (int co = 0; co < CO; co++)
                c += convb[co] * fsm[co * NROUTES + t];
            g_const[t] = c;
        }
        __threadfence();
        __syncthreads();
        if (t == 0) atomicExch(&g_flag, 1);
        return;
    }

    // ---------------- worker block: one 4-row chunk -----------------------
    const int chunkid = blockIdx.x - 1;
    const int b     = chunkid / CHUNKS;
    const int chunk = chunkid - b * CHUNKS;
    const int row_i = t >> 6;            // 0..3
    const int cq    = t & 63;            // channel quad
    const int r     = chunk * 4 + row_i;

    const float4* row = in + ((size_t)(b * HH + r) * WW) * (CC / 4) + cq;

    float4 se = make_float4(0.f, 0.f, 0.f, 0.f);
    float4 so = make_float4(0.f, 0.f, 0.f, 0.f);
    const float4 v0 = row[0];
    #pragma unroll 7
    for (int p = 0; p < 28; p++) {
        const float4 e = row[(size_t)(2 * p)     * (CC / 4)];
        const float4 o = row[(size_t)(2 * p + 1) * (CC / 4)];
        se.x += e.x; se.y += e.y; se.z += e.z; se.w += e.w;
        so.x += o.x; so.y += o.y; so.z += o.z; so.w += o.w;
    }

    float4* smv = (float4*)sm;
    smv[(row_i * 3 + 0) * 64 + cq] = se;
    smv[(row_i * 3 + 1) * 64 + cq] = so;
    smv[(row_i * 3 + 2) * 64 + cq] = v0;
    __syncthreads();

    const int ch = t;
    #define SM(row, slot) sm[((row) * 3 + (slot)) * CC + ch]
    const float se0 = SM(0,0), se1 = SM(1,0), se2 = SM(2,0), se3 = SM(3,0);
    const float so0 = SM(0,1), so1 = SM(1,1), so2 = SM(2,1), so3 = SM(3,1);
    const float v00 = SM(0,2), v01 = SM(1,2), v02 = SM(2,2), v03 = SM(3,2);
    #undef SM

    const float zf = (chunk == 0) ? 1.f : 0.f;
    const float t00 = se0 + se2, t01 = so0 + so2;
    const float t10 = se1 + se3, t11 = so1 + so3;
    const float r0e = zf * se0,  r0o = zf * so0;
    const float c0e = v00 + v02, c0o = v01 + v03;
    const float crn = zf * v00;

    // per-chunk tap sums (linear in partials; zf gates boundary terms)
    const float S[9] = { t00, t01, t00 - c0e,
                         t10, t11, t10 - c0o,
                         t00 - r0e, t01 - r0o, t00 - c0e - r0e + crn };
    const float cnt[9] = { 784.f, 784.f, 756.f, 784.f, 784.f, 756.f,
                           756.f, 756.f, 729.f };

    const float a  = gamma[ch] * rsqrtf(mvar[ch] + 1e-3f);
    const float bc = beta[ch] - mmean[ch] * a;

    // wait for W2 (duty block bid 0 is wave-1 resident; flag set ~30us ago)
    if (t == 0) {
        while (atomicAdd(&g_flag, 0) == 0) __nanosleep(64);
    }
    __syncthreads();

    float4 acc = make_float4(0.f, 0.f, 0.f, 0.f);
    #pragma unroll
    for (int k = 0; k < 9; k++) {
        const float sbn = a * S[k] + zf * (bc * cnt[k]);  // offset applied once (chunk 0)
        const float4 w = __ldcg((const float4*)&g_w2[(k * CC + ch) * NROUTES]);
        acc.x += sbn * w.x; acc.y += sbn * w.y;
        acc.z += sbn * w.z; acc.w += sbn * w.w;
    }

    __shared__ float4 red[256];
    red[t] = acc;
    __syncthreads();
    for (int off = 128; off >= 32; off >>= 1) {
        if (t < off) {
            float4 o = red[t + off];
            red[t].x += o.x; red[t].y += o.y; red[t].z += o.z; red[t].w += o.w;
        }
        __syncthreads();
    }
    if (t < 32) {
        float4 v = red[t];
        #pragma unroll
        for (int off = 16; off >= 1; off >>= 1) {
            v.x += __shfl_down_sync(0xffffffffu, v.x, off);
            v.y += __shfl_down_sync(0xffffffffu, v.y, off);
            v.z += __shfl_down_sync(0xffffffffu, v.z, off);
            v.w += __shfl_down_sync(0xffffffffu, v.w, off);
        }
        if (t == 0) {
            atomicAdd(&g_routing[b * NROUTES + 0], v.x);
            atomicAdd(&g_routing[b * NROUTES + 1], v.y);
            atomicAdd(&g_routing[b * NROUTES + 2], v.z);
            atomicAdd(&g_routing[b * NROUTES + 3], v.w);
        }
    }
}

// ---------------------------------------------------------------------------
// Kernel 2: gather + per-block argmax. grid (49, 64). Each block reads the
// 4 accumulated logits (+const), argmaxes locally, copies its slice of the
// selected 64-channel quarter. Block (0,b) also writes routing_x; block
// (0,0) resets the w2 flag for the next graph replay.
// ---------------------------------------------------------------------------
__global__ void gather_kernel(const float4* __restrict__ in,
                              float4* __restrict__ out) {
    const int b = blockIdx.y;

    float rv[NROUTES];
    #pragma unroll
    for (int r = 0; r < NROUTES; r++)
        rv[r] = g_routing[b * NROUTES + r] + g_const[r];
    int rt = 0; float bv = rv[0];
    #pragma unroll
    for (int r = 1; r < NROUTES; r++)
        if (rv[r] > bv) { bv = rv[r]; rt = r; }

    if (blockIdx.x == 0) {
        if (threadIdx.x < NROUTES)
            ((float*)out)[(size_t)X_ELEMS + b * NROUTES + threadIdx.x] =
                rv[threadIdx.x];
        if (b == 0 && threadIdx.x == 0) g_flag = 0;   // reset for next replay
    }

    const int rt16 = rt * 16;
    const size_t bbase = (size_t)b * (HH * WW) * 16;   // float4 units of x

    const int f0 = blockIdx.x * 1024 + threadIdx.x;
    float4 v[4];
    #pragma unroll
    for (int i = 0; i < 4; i++) {
        const int f = f0 + i * 256;
        const int p = f >> 4;
        const int j = f & 15;
        v[i] = __ldg(&in[bbase * 4 + (size_t)p * 64 + rt16 + j]);
    }
    #pragma unroll
    for (int i = 0; i < 4; i++)
        out[bbase + f0 + i * 256] = v[i];
}

// ---------------------------------------------------------------------------
extern "C" void kernel_launch(void* const* d_in, const int* in_sizes, int n_in,
                              void* d_out, int out_size) {
    const float* inputs = (const float*)d_in[0];
    const float* gamma  = (const float*)d_in[1];
    const float* beta   = (const float*)d_in[2];
    const float* mmean  = (const float*)d_in[3];
    const float* mvar   = (const float*)d_in[4];
    const float* convw  = (const float*)d_in[5];
    const float* convb  = (const float*)d_in[6];
    const float* fcw    = (const float*)d_in[7];
    const float* fcb    = (const float*)d_in[8];

    reduce_route_kernel<<<BB * CHUNKS + 1, 256>>>(
        (const float4*)inputs, gamma, beta, mmean, mvar,
        convw, convb, fcw, fcb);
    gather_kernel<<<dim3(49, BB), 256>>>((const float4*)inputs,
                                         (float4*)d_out);
}

// round 7
// speedup vs baseline: 1.9558x; 1.9558x over previous
#include <cuda_runtime.h>

#define BB 64
#define HH 56
#define WW 56
#define CC 256
#define CO 64
#define NROUTES 4
#define CHUNKS 14
#define X_ELEMS (BB*HH*WW*CO)   // 12,845,056

// scratch (device globals; no allocation allowed)
__device__ float g_part[CHUNKS * 9 * BB * CC];   // 8.26 MB partial sums
__device__ float g_w2[9 * CC * NROUTES];          // conv_w @ fc_w / 784
__device__ float g_const[NROUTES];                // conv_b @ fc_w + fc_b
__device__ int   g_route[BB];

// ---------------------------------------------------------------------------
// w2 slice: W2[k][ci][r] = (1/784) * sum_co convw[k][ci][co] * fcw[co][r]
// ---------------------------------------------------------------------------
__device__ __forceinline__ void w2_work(int k,
                                        const float* __restrict__ convw,
                                        const float* __restrict__ convb,
                                        const float* __restrict__ fcw,
                                        const float* __restrict__ fcb,
                                        float* fsm) {
    const int t = threadIdx.x;
    if (t < CO * NROUTES) fsm[t] = fcw[t];
    __syncthreads();

    if (k < 9) {
        const int ci = t;
        const float* wrow = convw + ((size_t)k * CC + ci) * CO;
        float acc[NROUTES] = {0.f, 0.f, 0.f, 0.f};
        #pragma unroll 8
        for (int co = 0; co < CO; co++) {
            const float w = wrow[co];
            #pragma unroll
            for (int r = 0; r < NROUTES; r++)
                acc[r] += w * fsm[co * NROUTES + r];
        }
        #pragma unroll
        for (int r = 0; r < NROUTES; r++)
            g_w2[(k * CC + ci) * NROUTES + r] = acc[r] * (1.0f / 784.0f);
    } else if (t < NROUTES) {
        float c = fcb[t];
        for (int co = 0; co < CO; co++)
            c += convb[co] * fsm[co * NROUTES + t];
        g_const[t] = c;
    }
}

// ---------------------------------------------------------------------------
// Kernel 1: parity sums (+ merged w2 blocks at blockIdx.y == CHUNKS).
// grid (64, 15), 256 threads. Reduce blocks: each 64-thread group handles one
// row (float4 = 4 channels/thread); smem reduce across 4 rows; coalesced
// partial write. Input read with evict-first (streamed once).
// ---------------------------------------------------------------------------
__global__ void reduce_kernel(const float4* __restrict__ in,
                              const float* __restrict__ convw,
                              const float* __restrict__ convb,
                              const float* __restrict__ fcw,
                              const float* __restrict__ fcb) {
    __shared__ float sm[4 * 3 * CC];

    const int chunk = blockIdx.y;
    if (chunk == CHUNKS) {                 // w2 duty blocks
        if (blockIdx.x < 10)
            w2_work(blockIdx.x, convw, convb, fcw, fcb, sm);
        return;
    }

    const int b     = blockIdx.x;
    const int t     = threadIdx.x;
    const int row_i = t >> 6;        // 0..3
    const int cq    = t & 63;        // channel quad
    const int r     = chunk * 4 + row_i;

    const float4* row = in + ((size_t)(b * HH + r) * WW) * (CC / 4) + cq;

    float4 se = make_float4(0.f, 0.f, 0.f, 0.f);
    float4 so = make_float4(0.f, 0.f, 0.f, 0.f);
    const float4 v0 = __ldcs(&row[0]);
    #pragma unroll
    for (int p = 0; p < 28; p++) {
        const float4 e = __ldcs(&row[(size_t)(2 * p)     * (CC / 4)]);
        const float4 o = __ldcs(&row[(size_t)(2 * p + 1) * (CC / 4)]);
        se.x += e.x; se.y += e.y; se.z += e.z; se.w += e.w;
        so.x += o.x; so.y += o.y; so.z += o.z; so.w += o.w;
    }

    float4* smv = (float4*)sm;
    smv[(row_i * 3 + 0) * 64 + cq] = se;
    smv[(row_i * 3 + 1) * 64 + cq] = so;
    smv[(row_i * 3 + 2) * 64 + cq] = v0;
    __syncthreads();

    const int ch = t;
    #define SM(row, slot) sm[((row) * 3 + (slot)) * CC + ch]
    const float se0 = SM(0,0), se1 = SM(1,0), se2 = SM(2,0), se3 = SM(3,0);
    const float so0 = SM(0,1), so1 = SM(1,1), so2 = SM(2,1), so3 = SM(3,1);
    const float v00 = SM(0,2), v01 = SM(1,2), v02 = SM(2,2), v03 = SM(3,2);
    #undef SM

    const float zf = (chunk == 0) ? 1.f : 0.f;
    float outv[9];
    outv[0] = se0 + se2;        // t00 (even row, even col)
    outv[1] = so0 + so2;        // t01
    outv[2] = se1 + se3;        // t10
    outv[3] = so1 + so3;        // t11
    outv[4] = zf * se0;         // r0e
    outv[5] = zf * so0;         // r0o
    outv[6] = v00 + v02;        // c0e
    outv[7] = v01 + v03;        // c0o
    outv[8] = zf * v00;         // crn

    #pragma unroll
    for (int s = 0; s < 9; s++)
        g_part[(((size_t)chunk * 9 + s) * BB + b) * CC + ch] = outv[s];
}

// ---------------------------------------------------------------------------
// Kernel 2: per-batch routing. 64 blocks x 256 threads (thread = ci).
// ---------------------------------------------------------------------------
__global__ void route_kernel(const float* __restrict__ gamma,
                             const float* __restrict__ beta,
                             const float* __restrict__ mmean,
                             const float* __restrict__ mvar,
                             float* __restrict__ dout) {
    const int b = blockIdx.x;
    const int t = threadIdx.x;   // ci

    float s[9];
    #pragma unroll
    for (int k = 0; k < 9; k++) s[k] = 0.f;
    for (int chunk = 0; chunk < CHUNKS; chunk++) {
        #pragma unroll
        for (int k = 0; k < 9; k++)
            s[k] += __ldcs(&g_part[(((size_t)chunk * 9 + k) * BB + b) * CC + t]);
    }
    const float a  = gamma[t] * rsqrtf(mvar[t] + 1e-3f);
    const float bc = beta[t] - mmean[t] * a;

    const float T00 = s[0], T01 = s[1], T10 = s[2], T11 = s[3];
    const float R0E = s[4], R0O = s[5], C0E = s[6], C0O = s[7], CRN = s[8];
    const float S[9] = { T00, T01, T00 - C0E,
                         T10, T11, T10 - C0O,
                         T00 - R0E, T01 - R0O, T00 - C0E - R0E + CRN };
    const float cnt[9] = { 784.f, 784.f, 756.f, 784.f, 784.f, 756.f,
                           756.f, 756.f, 729.f };

    float4 acc = make_float4(0.f, 0.f, 0.f, 0.f);
    #pragma unroll
    for (int k = 0; k < 9; k++) {
        const float sbn = a * S[k] + bc * cnt[k];
        const float4 w = *(const float4*)&g_w2[(k * CC + t) * NROUTES];
        acc.x += sbn * w.x; acc.y += sbn * w.y;
        acc.z += sbn * w.z; acc.w += sbn * w.w;
    }

    __shared__ float4 red[256];
    red[t] = acc;
    __syncthreads();
    for (int off = 128; off >= 32; off >>= 1) {
        if (t < off) {
            float4 o = red[t + off];
            red[t].x += o.x; red[t].y += o.y; red[t].z += o.z; red[t].w += o.w;
        }
        __syncthreads();
    }
    if (t < 32) {
        float4 v = red[t];
        #pragma unroll
        for (int off = 16; off >= 1; off >>= 1) {
            v.x += __shfl_down_sync(0xffffffffu, v.x, off);
            v.y += __shfl_down_sync(0xffffffffu, v.y, off);
            v.z += __shfl_down_sync(0xffffffffu, v.z, off);
            v.w += __shfl_down_sync(0xffffffffu, v.w, off);
        }
        if (t == 0) {
            float rv[NROUTES] = { v.x + g_const[0], v.y + g_const[1],
                                  v.z + g_const[2], v.w + g_const[3] };
            int best = 0; float bv = rv[0];
            #pragma unroll
            for (int r = 1; r < NROUTES; r++)
                if (rv[r] > bv) { bv = rv[r]; best = r; }
            g_route[b] = best;
            #pragma unroll
            for (int r = 0; r < NROUTES; r++)
                dout[(size_t)X_ELEMS + b * NROUTES + r] = rv[r];
        }
    }
}

// ---------------------------------------------------------------------------
// Kernel 3: gather. grid (49, 64): y = batch (no divide), 4 float4 per
// thread, front-batched loads (MLP=4), coalesced 256B read / contiguous write.
// ---------------------------------------------------------------------------
__global__ void gather_kernel(const float4* __restrict__ in,
                              float4* __restrict__ out) {
    const int b = blockIdx.y;
    const int rt16 = g_route[b] * 16;
    const size_t bbase = (size_t)b * (HH * WW) * 16;   // float4 units of x

    const int f0 = blockIdx.x * 1024 + threadIdx.x;
    float4 v[4];
    #pragma unroll
    for (int i = 0; i < 4; i++) {
        const int f = f0 + i * 256;
        const int p = f >> 4;
        const int j = f & 15;
        v[i] = __ldcs(&in[bbase * 4 + (size_t)p * 64 + rt16 + j]);
    }
    #pragma unroll
    for (int i = 0; i < 4; i++)
        out[bbase + f0 + i * 256] = v[i];
}

// ---------------------------------------------------------------------------
extern "C" void kernel_launch(void* const* d_in, const int* in_sizes, int n_in,
                              void* d_out, int out_size) {
    const float* inputs = (const float*)d_in[0];
    const float* gamma  = (const float*)d_in[1];
    const float* beta   = (const float*)d_in[2];
    const float* mmean  = (const float*)d_in[3];
    const float* mvar   = (const float*)d_in[4];
    const float* convw  = (const float*)d_in[5];
    const float* convb  = (const float*)d_in[6];
    const float* fcw    = (const float*)d_in[7];
    const float* fcb    = (const float*)d_in[8];
    float* out = (float*)d_out;

    reduce_kernel<<<dim3(BB, CHUNKS + 1), 256>>>((const float4*)inputs,
                                                 convw, convb, fcw, fcb);
    route_kernel<<<BB, 256>>>(gamma, beta, mmean, mvar, out);
    gather_kernel<<<dim3(49, BB), 256>>>((const float4*)inputs, (float4*)out);
}